// round 16
// baseline (speedup 1.0000x reference)
#include <cuda_runtime.h>
#include <cstdint>

#define RADIUS 5
#define KS 11
#define IMG_H 256
#define IMG_W 256
#define HW (IMG_H * IMG_W)
#define BX 16
#define BYT 2            // ty; each thread owns output rows 2ty, 2ty+1
#define TZ 4             // window split: 3 of 12 rows per tz
#define OUTY 4           // output rows per block
#define TX 26            // halo width (16 + 10)
#define TYR 14           // halo height (4 + 10)
#define PLANE (TYR * TX) // 364
// per-pixel smem: G0(16) G1(16) E(16: se0,se1,N0,N1) F(16: se2,N2,i0,i1)
//                 H(8: i2,Q)  -> 72 B
#define SMEM_BYTES (PLANE * 72)
#define OFF_G1 (16 * PLANE)
#define OFF_E  (32 * PLANE)
#define OFF_F  (48 * PLANE)
#define OFF_H  (64 * PLANE)

__device__ __forceinline__ float ex2f(float x) {
    float r; asm("ex2.approx.f32 %0, %1;" : "=f"(r) : "f"(x)); return r;
}
// packed f32x2 helpers
__device__ __forceinline__ uint64_t pk2(float lo, float hi) {
    uint64_t r; asm("mov.b64 %0, {%1,%2};" : "=l"(r) : "f"(lo), "f"(hi)); return r;
}
__device__ __forceinline__ void unpk2(float& lo, float& hi, uint64_t v) {
    asm("mov.b64 {%0,%1}, %2;" : "=f"(lo), "=f"(hi) : "l"(v));
}
__device__ __forceinline__ uint64_t add2(uint64_t a, uint64_t b) {
    uint64_t d; asm("add.rn.f32x2 %0,%1,%2;" : "=l"(d) : "l"(a), "l"(b)); return d;
}
__device__ __forceinline__ uint64_t mul2(uint64_t a, uint64_t b) {
    uint64_t d; asm("mul.rn.f32x2 %0,%1,%2;" : "=l"(d) : "l"(a), "l"(b)); return d;
}
__device__ __forceinline__ uint64_t fma2(uint64_t a, uint64_t b, uint64_t c) {
    uint64_t d; asm("fma.rn.f32x2 %0,%1,%2,%3;" : "=l"(d) : "l"(a), "l"(b), "l"(c)); return d;
}

// ---------------------------------------------------------------------------
// f32 ndtri replicating jax.scipy.special.ndtri (cephes, no FMA contraction).
// ---------------------------------------------------------------------------
template <int N>
__device__ __forceinline__ float polevl_f(float x, const float (&c)[N]) {
    float r = c[0];
#pragma unroll
    for (int i = 1; i < N; ++i) r = __fadd_rn(__fmul_rn(r, x), c[i]);
    return r;
}

__device__ float ndtri_f32(float p) {
    const float P0[5] = {-5.99633501014107895267e1f, 9.80010754185999661536e1f,
                         -5.66762857469070293439e1f, 1.39312609387279679503e1f,
                         -1.23916583867381258016e0f};
    const float Q0[9] = {1.0f, 1.95448858338141759834e0f, 4.67627912898881538453e0f,
                         8.63602421390890590575e1f, -2.25462687854119370527e2f,
                         2.00260212380060660359e2f, -8.20372256168538034246e1f,
                         1.59056225126211695515e1f, -1.18331621121330003142e0f};
    const float P1c[9] = {4.05544892305962419923e0f, 3.15251094599893866154e1f,
                          5.71628192246421288162e1f, 4.40805073893200834700e1f,
                          1.46849561928858024014e1f, 2.18663306850790267539e0f,
                          -1.40256079171354495875e-1f, -3.50424626827848203418e-2f,
                          -8.57456785154685413611e-4f};
    const float Q1c[9] = {1.0f, 1.57799883256466749731e1f, 4.53907635128879210584e1f,
                          4.13172038254672030440e1f, 1.50425385692907503408e1f,
                          2.50464946208309415979e0f, -1.42182922854787788574e-1f,
                          -3.80806407691578277194e-2f, -9.33259480895457427372e-4f};
    const float P2c[9] = {3.23774891776946035970e0f, 6.91522889068984211695e0f,
                          3.93881025292474443415e0f, 1.33303460815807542389e0f,
                          2.01485389549179081538e-1f, 1.23716634817820021358e-2f,
                          3.01581553508235416007e-4f, 2.65806974686737550832e-6f,
                          6.23974539184983651783e-9f};
    const float Q2c[9] = {1.0f, 6.02427039364742014255e0f, 3.67983563856160859403e0f,
                          1.37702099489081330271e0f, 2.16236993594496635890e-1f,
                          1.34204006088543189037e-2f, 3.28014464682127739104e-4f,
                          2.89247864745380683936e-6f, 6.79019408009981274425e-9f};
    const float one_m_expm2 = 0.86466471676338730811f;
    const float expm2 = 0.13533528323661269189f;

    float mcp = (p > one_m_expm2) ? __fadd_rn(1.0f, -p) : p;
    float san = (mcp <= 0.0f) ? 0.5f : mcp;
    float x;
    if (san > expm2) {
        float w = __fadd_rn(san, -0.5f);
        float ww = __fmul_rn(w, w);
        float r = __fdiv_rn(polevl_f(ww, P0), polevl_f(ww, Q0));
        x = __fadd_rn(w, __fmul_rn(__fmul_rn(w, ww), r));
        x = __fmul_rn(x, -2.50662827463100050242f);
    } else {
        float z = __fsqrt_rn(__fmul_rn(-2.0f, logf(san)));
        float ft = __fadd_rn(z, -__fdiv_rn(logf(z), z));
        float iz = __fdiv_rn(1.0f, z);
        float num, den;
        if (z >= 8.0f) { num = polevl_f(iz, P2c); den = polevl_f(iz, Q2c); }
        else           { num = polevl_f(iz, P1c); den = polevl_f(iz, Q1c); }
        float st = __fdiv_rn(__fdiv_rn(num, den), z);
        x = __fadd_rn(ft, -st);
    }
    return (p > one_m_expm2) ? x : -x;
}

__device__ float compute_gamma(int spp) {
    float z = ndtri_f32(0.9975f);
    double df = (double)(2 * spp - 2);
    float z2 = __fmul_rn(z, z);
    float z3 = __fmul_rn(z, z2);
    float z4 = __fmul_rn(z2, z2);
    float z5 = __fmul_rn(z, z4);
    float z7 = __fmul_rn(z3, z4);
    float g1 = __fdiv_rn(__fadd_rn(z3, z), (float)(4.0 * df));
    float g2 = __fdiv_rn(
        __fadd_rn(__fadd_rn(__fmul_rn(5.0f, z5), __fmul_rn(16.0f, z3)), __fmul_rn(3.0f, z)),
        (float)(96.0 * df * df));
    float g3 = __fdiv_rn(
        __fadd_rn(__fadd_rn(__fadd_rn(__fmul_rn(3.0f, z7), __fmul_rn(19.0f, z5)),
                            __fmul_rn(17.0f, z3)),
                  -__fmul_rn(15.0f, z)),
        (float)(384.0 * df * df * df));
    return __fadd_rn(__fadd_rn(__fadd_rn(z, g1), g2), g3);
}

// ---------------------------------------------------------------------------
// Denoiser: expanded quadratics + packed f32x2 (R15 body), rebalanced grid.
//   bilateral: arg = 2*dot(gn,gc) - Qn - Qc  (dot via mul2+3xfma2)
//   membership: r = C + N + 2*ce*se; ch0/1 packed, ch2 scalar
// block (16,2,4)=128 thr, 1024 blocks, 16x4 tile; launch_bounds(128,8):
// single wave (1184 slots >= 1024), per-SM balance 7 vs 6.92 (1.01 vs 1.16).
// ---------------------------------------------------------------------------
__global__ void __launch_bounds__(128, 8)
denoise_kernel(const float* __restrict__ img, const float* __restrict__ gd,
               const float* __restrict__ est, const float* __restrict__ var,
               const int* __restrict__ spp_p, float* __restrict__ out) {
    extern __shared__ char smraw[];
    float4* G0 = (float4*)smraw;
    float4* G1 = (float4*)(smraw + OFF_G1);
    float4* E  = (float4*)(smraw + OFF_E);   // se0, se1, N0, N1
    float4* F  = (float4*)(smraw + OFF_F);   // se2, N2, i0, i1
    float2* H  = (float2*)(smraw + OFF_H);   // i2, Q

    const int tx = threadIdx.x, ty = threadIdx.y, tz = threadIdx.z;
    const int tid = (tz * BYT + ty) * BX + tx;
    const int gx0 = blockIdx.x * BX - RADIUS;
    const int gy0 = blockIdx.y * OUTY - RADIUS;
    const float NINF = __int_as_float(0xff800000);
    // sqrt(0.5 * sigma_c * log2(e))
    const float SCA = 0.26857906f;   // sigma 0.1
    const float SCB = 6.00561167f;   // sigma 50
    const float SCC = 2.68579063f;   // sigma 10

    // gamma^2: uniform, computed by every thread (no divergence, once).
    const float gm = compute_gamma(spp_p[0]);
    const float g2 = gm * gm;

    for (int i = tid; i < PLANE; i += 128) {
        int ly = i / TX, lx = i - ly * TX;
        int gy = gy0 + ly, gx = gx0 + lx;
        bool inb = ((unsigned)gy < IMG_H) & ((unsigned)gx < IMG_W);
        int g = gy * IMG_W + gx;
        float4 a, b, e4, f4; float2 h2;
        if (inb) {
            a = make_float4(gd[g] * SCA, gd[HW + g] * SCA,
                            gd[2 * HW + g] * SCB, gd[3 * HW + g] * SCB);
            b = make_float4(gd[4 * HW + g] * SCB, gd[5 * HW + g] * SCC,
                            gd[6 * HW + g] * SCC, gd[7 * HW + g] * SCC);
            float Q = a.x * a.x;
            Q = fmaf(a.y, a.y, Q); Q = fmaf(a.z, a.z, Q); Q = fmaf(a.w, a.w, Q);
            Q = fmaf(b.x, b.x, Q); Q = fmaf(b.y, b.y, Q);
            Q = fmaf(b.z, b.z, Q); Q = fmaf(b.w, b.w, Q);
            float e0 = est[g], e1 = est[HW + g], e2 = est[2 * HW + g];
            float v0 = var[g], v1 = var[HW + g], v2 = var[2 * HW + g];
            float N0 = (v0 == 0.f) ? NINF : fmaf(g2, v0, -(e0 * e0));
            float N1 = (v1 == 0.f) ? NINF : fmaf(g2, v1, -(e1 * e1));
            float N2 = (v2 == 0.f) ? NINF : fmaf(g2, v2, -(e2 * e2));
            e4 = make_float4(e0, e1, N0, N1);
            f4 = make_float4(e2, N2, img[g], img[HW + g]);
            h2 = make_float2(img[2 * HW + g], Q);
        } else {
            a = make_float4(0.f, 0.f, 0.f, 0.f); b = a;
            e4 = make_float4(0.f, 0.f, NINF, NINF);
            f4 = make_float4(0.f, NINF, 0.f, 0.f);
            h2 = make_float2(0.f, 0.f);
        }
        G0[i] = a; G1[i] = b; E[i] = e4; F[i] = f4; H[i] = h2;
    }
    __syncthreads();
    const unsigned sbase = (unsigned)__cvta_generic_to_shared(smraw);

    // Center constants for both owned pixels (rows 2ty, 2ty+1).
    const int ci0 = (2 * ty + RADIUS) * TX + tx + RADIUS;
    const int ci1 = ci0 + TX;
    const float4 cga = G0[ci0], cgb = G1[ci0];
    const float4 cha = G0[ci1], chb = G1[ci1];
    const uint64_t c0a = pk2(cga.x, cga.y), c0b = pk2(cga.z, cga.w);
    const uint64_t c0c = pk2(cgb.x, cgb.y), c0d = pk2(cgb.z, cgb.w);
    const uint64_t c1a = pk2(cha.x, cha.y), c1b = pk2(cha.z, cha.w);
    const uint64_t c1c = pk2(chb.x, chb.y), c1d = pk2(chb.z, chb.w);
    const float nQ0 = -H[ci0].y, nQ1 = -H[ci1].y;
    const float4 ce0 = E[ci0], cf0 = F[ci0];
    const float4 ce1 = E[ci1], cf1 = F[ci1];
    // packed (2*ce0, 2*ce1) and packed center C01 = (N0c, N1c)
    const uint64_t w01_0 = pk2(2.f * ce0.x, 2.f * ce0.y);
    const uint64_t C01_0 = pk2(ce0.z, ce0.w);
    const uint64_t w01_1 = pk2(2.f * ce1.x, 2.f * ce1.y);
    const uint64_t C01_1 = pk2(ce1.z, ce1.w);
    const float w02 = 2.f * cf0.x, C02 = cf0.y;
    const float w12 = 2.f * cf1.x, C12 = cf1.y;

    float sw0 = 0.f, a00 = 0.f, a01 = 0.f, a02 = 0.f;
    float sw1 = 0.f, a10 = 0.f, a11 = 0.f, a12 = 0.f;
    const int rstart = tz * 3;

#pragma unroll
    for (int rr = 0; rr < 3; ++rr) {
        const int r = rstart + rr;                  // 0..11 over the 12-row span
        const bool act0 = (r <= 10), act1 = (r >= 1);
        const bool f0 = (r == RADIUS), f1 = (r == RADIUS + 1);
        const int rowb = (2 * ty + r) * TX + tx;
        const unsigned ga = sbase + (unsigned)(rowb * 16);
#pragma unroll
        for (int dx = 0; dx < KS; ++dx) {
            const int ni = rowb + dx;
            uint64_t g01, g23, g45, g67, se01, N01;
            asm("ld.shared.v2.u64 {%0,%1}, [%2];"
                : "=l"(g01), "=l"(g23) : "r"(ga + dx * 16));
            asm("ld.shared.v2.u64 {%0,%1}, [%2];"
                : "=l"(g45), "=l"(g67) : "r"(ga + dx * 16 + OFF_G1));
            asm("ld.shared.v2.u64 {%0,%1}, [%2];"
                : "=l"(se01), "=l"(N01) : "r"(ga + dx * 16 + OFF_E));
            const float4 f = F[ni];                 // se2,N2,i0,i1
            const float2 h = H[ni];                 // i2,Q

            // bilateral, center 0: packed dot, arg = 2*(se+so) - Qn - Qc
            uint64_t p0 = mul2(g01, c0a);
            p0 = fma2(g23, c0b, p0);
            p0 = fma2(g45, c0c, p0);
            p0 = fma2(g67, c0d, p0);
            float s0e, s0o; unpk2(s0e, s0o, p0);
            float bw0 = ex2f(fmaf(s0e + s0o, 2.f, nQ0 - h.y));
            // bilateral, center 1
            uint64_t p1 = mul2(g01, c1a);
            p1 = fma2(g23, c1b, p1);
            p1 = fma2(g45, c1c, p1);
            p1 = fma2(g67, c1d, p1);
            float s1e, s1o; unpk2(s1e, s1o, p1);
            float bw1 = ex2f(fmaf(s1e + s1o, 2.f, nQ1 - h.y));

            // membership: ch0/1 packed, ch2 scalar; r = C + N + 2*ce*se > 0
            uint64_t r01 = fma2(w01_0, se01, add2(C01_0, N01));
            float r0, r1; unpk2(r0, r1, r01);
            float r2 = fmaf(w02, f.x, C02 + f.y);
            bool mem0 = fminf(fminf(r0, r1), r2) > 0.f;
            r01 = fma2(w01_1, se01, add2(C01_1, N01));
            unpk2(r0, r1, r01);
            r2 = fmaf(w12, f.x, C12 + f.y);
            bool mem1 = fminf(fminf(r0, r1), r2) > 0.f;

            if (dx == RADIUS) {                      // force own center pixel in
                mem0 = mem0 | f0;
                mem1 = mem1 | f1;
            }
            mem0 = mem0 & act0;
            mem1 = mem1 & act1;
            float fw0 = mem0 ? bw0 : 0.f;
            float fw1 = mem1 ? bw1 : 0.f;
            sw0 += fw0;
            a00 = fmaf(f.z, fw0, a00); a01 = fmaf(f.w, fw0, a01); a02 = fmaf(h.x, fw0, a02);
            sw1 += fw1;
            a10 = fmaf(f.z, fw1, a10); a11 = fmaf(f.w, fw1, a11); a12 = fmaf(h.x, fw1, a12);
        }
    }

    // 4-way tz reduction through smem (conflict-free layout R[tz*64 + pix]).
    __syncthreads();
    float4* R = (float4*)smraw;
    const int pix0 = (2 * ty) * BX + tx;            // 0..63 over the 16x4 tile
    R[tz * 64 + pix0] = make_float4(sw0, a00, a01, a02);
    R[tz * 64 + pix0 + BX] = make_float4(sw1, a10, a11, a12);
    __syncthreads();
    if (tid < 64) {
        float4 u = R[tid], v = R[64 + tid], w = R[128 + tid], x = R[192 + tid];
        float swt = (u.x + v.x) + (w.x + x.x);
        float inv = __fdiv_rn(1.0f, fmaxf(swt, 1e-10f));
        int ox = blockIdx.x * BX + (tid & 15);
        int oy = blockIdx.y * OUTY + (tid >> 4);
        int o = oy * IMG_W + ox;
        out[o] = ((u.y + v.y) + (w.y + x.y)) * inv;
        out[HW + o] = ((u.z + v.z) + (w.z + x.z)) * inv;
        out[2 * HW + o] = ((u.w + v.w) + (w.w + x.w)) * inv;
    }
}

extern "C" void kernel_launch(void* const* d_in, const int* in_sizes, int n_in,
                              void* d_out, int out_size) {
    const float* img = (const float*)d_in[0];
    const float* gd  = (const float*)d_in[1];
    const float* est = (const float*)d_in[2];
    const float* var = (const float*)d_in[3];
    const int*   spp = (const int*)d_in[4];
    float* out = (float*)d_out;

    dim3 block(BX, BYT, TZ);
    dim3 grid(IMG_W / BX, IMG_H / OUTY);
    denoise_kernel<<<grid, block, SMEM_BYTES>>>(img, gd, est, var, spp, out);
}